// round 1
// baseline (speedup 1.0000x reference)
#include <cuda_runtime.h>
#include <cstdint>

#define NB   2
#define NT   2048
#define ND   1024
#define NHH  16
#define NHD  64
#define NM   (NB * NT)   // 4096 rows

// Scratch (device globals: allocation is forbidden)
__device__ float g_Q[NB * NHH * NT * NHD];   // [b,h,t,hd]
__device__ float g_K[NB * NHH * NT * NHD];
__device__ float g_V[NB * NHH * NT * NHD];
__device__ float g_C[NM * ND];               // ctx, [b*T+t, h*hd+d]

// ---------------------------------------------------------------------------
// GEMM: Out = A[4096x1024] @ W[1024x1024]
// MODE 0: scatter into per-head layout [b,h,t,hd]
// MODE 1: plain row-major + bias
// 128x128 block, BK=16, 256 threads, 8x8 per-thread tile (split 4+4 for
// conflict-free float4 smem reads).
// ---------------------------------------------------------------------------
template <int MODE>
__global__ void __launch_bounds__(256, 2) gemm_kernel(
    const float* __restrict__ A, const float* __restrict__ W,
    float* __restrict__ Out, const float* __restrict__ bias)
{
    __shared__ float As[16][132];   // [k][m], padded
    __shared__ float Bs[16][128];   // [k][n]

    const int tid = threadIdx.x;
    const int tx = tid & 15, ty = tid >> 4;
    const int m0 = blockIdx.y << 7;
    const int n0 = blockIdx.x << 7;

    float acc[8][8];
#pragma unroll
    for (int i = 0; i < 8; ++i)
#pragma unroll
        for (int j = 0; j < 8; ++j) acc[i][j] = 0.f;

    const int am = tid >> 2;          // 0..63 (m within half-tile)
    const int ak = (tid & 3) << 2;    // 0,4,8,12
    const int bk = tid >> 5;          // 0..7
    const int bn = (tid & 31) << 2;   // 0..124

    for (int k0 = 0; k0 < 1024; k0 += 16) {
#pragma unroll
        for (int h = 0; h < 2; ++h) {
            const int m = am + (h << 6);
            float4 v = *(const float4*)(A + (size_t)(m0 + m) * 1024 + k0 + ak);
            As[ak + 0][m] = v.x; As[ak + 1][m] = v.y;
            As[ak + 2][m] = v.z; As[ak + 3][m] = v.w;
        }
#pragma unroll
        for (int h = 0; h < 2; ++h) {
            const int k = bk + (h << 3);
            *(float4*)&Bs[k][bn] =
                *(const float4*)(W + (size_t)(k0 + k) * 1024 + n0 + bn);
        }
        __syncthreads();

#pragma unroll
        for (int k = 0; k < 16; ++k) {
            float a[8], b[8];
            *(float4*)(a)     = *(const float4*)&As[k][ty << 2];
            *(float4*)(a + 4) = *(const float4*)&As[k][64 + (ty << 2)];
            *(float4*)(b)     = *(const float4*)&Bs[k][tx << 2];
            *(float4*)(b + 4) = *(const float4*)&Bs[k][64 + (tx << 2)];
#pragma unroll
            for (int i = 0; i < 8; ++i)
#pragma unroll
                for (int j = 0; j < 8; ++j)
                    acc[i][j] = fmaf(a[i], b[j], acc[i][j]);
        }
        __syncthreads();
    }

#pragma unroll
    for (int i = 0; i < 8; ++i) {
        const int r = (i < 4) ? ((ty << 2) + i) : (64 + (ty << 2) + (i - 4));
        const int m = m0 + r;
#pragma unroll
        for (int jh = 0; jh < 2; ++jh) {
            const int c = (jh << 6) + (tx << 2);
            const int n = n0 + c;
            float4 v;
            v.x = acc[i][jh * 4 + 0]; v.y = acc[i][jh * 4 + 1];
            v.z = acc[i][jh * 4 + 2]; v.w = acc[i][jh * 4 + 3];
            if (MODE == 0) {
                const int bb = m >> 11, t = m & (NT - 1);
                const int hh = n >> 6,  d = n & 63;
                float* dst = Out + (((((size_t)bb * NHH + hh) * NT + t) << 6) + d);
                *(float4*)dst = v;
            } else {
                const float4 bv = *(const float4*)(bias + n);
                v.x += bv.x; v.y += bv.y; v.z += bv.z; v.w += bv.w;
                *(float4*)(Out + (size_t)m * 1024 + n) = v;
            }
        }
    }
}

// ---------------------------------------------------------------------------
// Causal flash attention, fp32. One block per (q-tile of 64 rows, b*H pair).
// 256 threads = 16x16 grid (tx,ty). Online softmax.
// S mapping: rows ty*4+i, cols tx+16*j  (conflict-free K float4 reads)
// PV mapping: rows ty*4+i, d = tx*4+j   (conflict-free V float4 reads)
// ---------------------------------------------------------------------------
__global__ void __launch_bounds__(256) attn_kernel(
    const uint8_t* __restrict__ kpm, float* __restrict__ Cctx)
{
    extern __shared__ float sm[];
    float* Qs = sm;               // 64 x 68
    float* Ks = Qs + 64 * 68;
    float* Vs = Ks + 64 * 68;
    float* Ps = Vs + 64 * 68;

    const int tid = threadIdx.x;
    const int tx = tid & 15, ty = tid >> 4;
    const int qt = blockIdx.x;
    const int bh = blockIdx.y;
    const int bb = bh >> 4, hh = bh & 15;
    const int q0 = qt << 6;

    const float* Qg = g_Q + ((size_t)bh * NT << 6);
    const float* Kg = g_K + ((size_t)bh * NT << 6);
    const float* Vg = g_V + ((size_t)bh * NT << 6);

    for (int f = tid; f < 64 * 16; f += 256) {
        const int r = f >> 4, d4 = (f & 15) << 2;
        *(float4*)&Qs[r * 68 + d4] = *(const float4*)&Qg[((q0 + r) << 6) + d4];
    }

    float m_i[4], l_i[4], o[4][4];
#pragma unroll
    for (int i = 0; i < 4; ++i) {
        m_i[i] = -1e30f; l_i[i] = 0.f;
#pragma unroll
        for (int j = 0; j < 4; ++j) o[i][j] = 0.f;
    }
    __syncthreads();

    for (int kt = 0; kt <= qt; ++kt) {
        const int k0 = kt << 6;
        for (int f = tid; f < 64 * 16; f += 256) {
            const int c = f >> 4, d4 = (f & 15) << 2;
            *(float4*)&Ks[c * 68 + d4] = *(const float4*)&Kg[((k0 + c) << 6) + d4];
            *(float4*)&Vs[c * 68 + d4] = *(const float4*)&Vg[((k0 + c) << 6) + d4];
        }
        __syncthreads();

        // ---- S = Q K^T for this tile ----
        float s[4][4];
#pragma unroll
        for (int i = 0; i < 4; ++i)
#pragma unroll
            for (int j = 0; j < 4; ++j) s[i][j] = 0.f;

#pragma unroll
        for (int d4 = 0; d4 < 16; ++d4) {
            float4 q4[4], k4[4];
#pragma unroll
            for (int i = 0; i < 4; ++i)
                q4[i] = *(const float4*)&Qs[((ty << 2) + i) * 68 + (d4 << 2)];
#pragma unroll
            for (int j = 0; j < 4; ++j)
                k4[j] = *(const float4*)&Ks[(tx + (j << 4)) * 68 + (d4 << 2)];
#pragma unroll
            for (int i = 0; i < 4; ++i)
#pragma unroll
                for (int j = 0; j < 4; ++j) {
                    s[i][j] = fmaf(q4[i].x, k4[j].x, s[i][j]);
                    s[i][j] = fmaf(q4[i].y, k4[j].y, s[i][j]);
                    s[i][j] = fmaf(q4[i].z, k4[j].z, s[i][j]);
                    s[i][j] = fmaf(q4[i].w, k4[j].w, s[i][j]);
                }
        }

        // ---- scale + masks ----
        int  kc[4]; bool pm[4];
#pragma unroll
        for (int j = 0; j < 4; ++j) {
            kc[j] = k0 + tx + (j << 4);
            pm[j] = (kpm[bb * NT + kc[j]] != 0);
        }
        const bool diag = (kt == qt);
#pragma unroll
        for (int i = 0; i < 4; ++i) {
            const int qr = q0 + (ty << 2) + i;
#pragma unroll
            for (int j = 0; j < 4; ++j) {
                float val = s[i][j] * 0.125f;           // 1/sqrt(64)
                if (pm[j] || (diag && kc[j] > qr)) val = -1e30f;
                s[i][j] = val;
            }
        }

        // ---- online softmax (row spread over 16 lanes) ----
#pragma unroll
        for (int i = 0; i < 4; ++i) {
            float m4 = fmaxf(fmaxf(s[i][0], s[i][1]), fmaxf(s[i][2], s[i][3]));
#pragma unroll
            for (int off = 1; off < 16; off <<= 1)
                m4 = fmaxf(m4, __shfl_xor_sync(0xffffffffu, m4, off));
            const float mn = fmaxf(m_i[i], m4);
            const float corr = __expf(m_i[i] - mn);
            m_i[i] = mn;
            float r = 0.f;
#pragma unroll
            for (int j = 0; j < 4; ++j) {
                const float p = __expf(s[i][j] - mn);
                s[i][j] = p;
                r += p;
            }
#pragma unroll
            for (int off = 1; off < 16; off <<= 1)
                r += __shfl_xor_sync(0xffffffffu, r, off);
            l_i[i] = l_i[i] * corr + r;
#pragma unroll
            for (int j = 0; j < 4; ++j) o[i][j] *= corr;
        }

#pragma unroll
        for (int i = 0; i < 4; ++i)
#pragma unroll
            for (int j = 0; j < 4; ++j)
                Ps[((ty << 2) + i) * 68 + tx + (j << 4)] = s[i][j];
        __syncthreads();

        // ---- O += P V ----
#pragma unroll
        for (int c4 = 0; c4 < 16; ++c4) {
            float4 p4[4];
#pragma unroll
            for (int i = 0; i < 4; ++i)
                p4[i] = *(const float4*)&Ps[((ty << 2) + i) * 68 + (c4 << 2)];
#pragma unroll
            for (int u = 0; u < 4; ++u) {
                const int c = (c4 << 2) + u;
                const float4 v4 = *(const float4*)&Vs[c * 68 + (tx << 2)];
#pragma unroll
                for (int i = 0; i < 4; ++i) {
                    const float p = ((const float*)&p4[i])[u];
                    o[i][0] = fmaf(p, v4.x, o[i][0]);
                    o[i][1] = fmaf(p, v4.y, o[i][1]);
                    o[i][2] = fmaf(p, v4.z, o[i][2]);
                    o[i][3] = fmaf(p, v4.w, o[i][3]);
                }
            }
        }
        __syncthreads();
    }

    // ---- normalize + write ctx in [b*T+t, h*64+d] layout ----
#pragma unroll
    for (int i = 0; i < 4; ++i) {
        const float inv = 1.f / l_i[i];
        const int m = (bb << 11) + q0 + (ty << 2) + i;
        float4 v;
        v.x = o[i][0] * inv; v.y = o[i][1] * inv;
        v.z = o[i][2] * inv; v.w = o[i][3] * inv;
        *(float4*)&Cctx[(size_t)m * ND + (hh << 6) + (tx << 2)] = v;
    }
}

// ---------------------------------------------------------------------------
extern "C" void kernel_launch(void* const* d_in, const int* in_sizes, int n_in,
                              void* d_out, int out_size)
{
    (void)in_sizes; (void)n_in; (void)out_size;
    const float*   x   = (const float*)d_in[0];
    const float*   Wq  = (const float*)d_in[1];
    const float*   Wk  = (const float*)d_in[2];
    const float*   Wv  = (const float*)d_in[3];
    const float*   Wo  = (const float*)d_in[4];
    const float*   bo  = (const float*)d_in[5];
    const uint8_t* kpm = (const uint8_t*)d_in[6];
    float* out = (float*)d_out;

    float *Qp, *Kp, *Vp, *Cp;
    cudaGetSymbolAddress((void**)&Qp, g_Q);
    cudaGetSymbolAddress((void**)&Kp, g_K);
    cudaGetSymbolAddress((void**)&Vp, g_V);
    cudaGetSymbolAddress((void**)&Cp, g_C);

    const dim3 gg(ND / 128, NM / 128);   // (8, 32)
    gemm_kernel<0><<<gg, 256>>>(x, Wq, Qp, nullptr);
    gemm_kernel<0><<<gg, 256>>>(x, Wk, Kp, nullptr);
    gemm_kernel<0><<<gg, 256>>>(x, Wv, Vp, nullptr);

    const int smem = 4 * 64 * 68 * (int)sizeof(float);  // 69632
    cudaFuncSetAttribute(attn_kernel, cudaFuncAttributeMaxDynamicSharedMemorySize, smem);
    attn_kernel<<<dim3(NT / 64, NB * NHH), 256, smem>>>(kpm, Cp);

    gemm_kernel<1><<<gg, 256>>>(Cp, Wo, out, bo);
}

// round 3
// speedup vs baseline: 2.6770x; 2.6770x over previous
#include <cuda_runtime.h>
#include <cstdint>

#define NB   2
#define NT   2048
#define ND   1024
#define NHH  16
#define NHD  64
#define NM   (NB * NT)   // 4096 rows

// Scratch (device globals: allocation is forbidden)
__device__ float g_Q[NB * NHH * NT * NHD];   // [b,h,t,hd]
__device__ float g_K[NB * NHH * NT * NHD];
__device__ float g_V[NB * NHH * NT * NHD];
__device__ float g_C[NM * ND];               // ctx, [b*T+t, h*hd+d]
__device__ float g_WT[4 * ND * ND];          // transposed weights [n][k]

// ---------------------------------------------------------------------------
// Helpers
// ---------------------------------------------------------------------------
__device__ __forceinline__ uint32_t f2tf32(float x) {
    uint32_t r; asm("cvt.rna.tf32.f32 %0, %1;" : "=r"(r) : "f"(x)); return r;
}

// mma.sync m16n8k8 row.col tf32: d += a * b
__device__ __forceinline__ void mma8(float* d, const uint32_t* a,
                                     uint32_t b0, uint32_t b1)
{
    asm volatile(
        "mma.sync.aligned.m16n8k8.row.col.f32.tf32.tf32.f32 "
        "{%0,%1,%2,%3}, {%4,%5,%6,%7}, {%8,%9}, {%0,%1,%2,%3};"
        : "+f"(d[0]), "+f"(d[1]), "+f"(d[2]), "+f"(d[3])
        : "r"(a[0]), "r"(a[1]), "r"(a[2]), "r"(a[3]), "r"(b0), "r"(b1));
}

// ---------------------------------------------------------------------------
// Weight transpose: WT[n][k] = W[k][n], 1024x1024
// ---------------------------------------------------------------------------
__global__ void transpose_w(const float* __restrict__ W, float* __restrict__ WT)
{
    __shared__ float t[32][33];
    const int x = (blockIdx.x << 5) + threadIdx.x;
    const int y0 = (blockIdx.y << 5) + threadIdx.y;
#pragma unroll
    for (int i = 0; i < 32; i += 8)
        t[threadIdx.y + i][threadIdx.x] = W[(size_t)(y0 + i) * ND + x];
    __syncthreads();
    const int x2 = (blockIdx.y << 5) + threadIdx.x;
    const int y2 = (blockIdx.x << 5) + threadIdx.y;
#pragma unroll
    for (int i = 0; i < 32; i += 8)
        WT[(size_t)(y2 + i) * ND + x2] = t[threadIdx.x][threadIdx.y + i];
}

// ---------------------------------------------------------------------------
// tf32 mma.sync GEMM: Out[4096x1024] = A @ W   (W given transposed BT[n][k])
// 128x128 block, BK=32, 256 thr = 8 warps (4m x 2n), warp tile 32x64.
// MODE 0: scatter to per-head [b,h,t,hd].  MODE 1: row-major + bias.
// ---------------------------------------------------------------------------
template <int MODE>
__global__ void __launch_bounds__(256) gemm_mma(
    const float* __restrict__ A, const float* __restrict__ BT,
    float* __restrict__ Out, const float* __restrict__ bias)
{
    __shared__ float As[128][36];   // [m][k], stride 36 (coeff 4 mod 32)
    __shared__ float Bs[128][36];   // [n][k]

    const int tid = threadIdx.x;
    const int lane = tid & 31;
    const int wid = tid >> 5;
    const int g = lane >> 2, t = lane & 3;
    const int wm = wid & 3;        // 0..3  (32 rows each)
    const int wn = wid >> 2;       // 0..1  (64 cols each)
    const int m0 = blockIdx.y << 7;
    const int n0 = blockIdx.x << 7;

    float acc[2][8][4];
#pragma unroll
    for (int mt = 0; mt < 2; ++mt)
#pragma unroll
        for (int nt = 0; nt < 8; ++nt)
#pragma unroll
            for (int e = 0; e < 4; ++e) acc[mt][nt][e] = 0.f;

    for (int c = 0; c < 32; ++c) {
        const int k0 = c << 5;
        float4 ra[4], rb[4];
#pragma unroll
        for (int u = 0; u < 4; ++u) {
            const int f = (u << 8) + tid;
            const int row = f >> 3, kc = (f & 7) << 2;
            ra[u] = *(const float4*)(A  + (size_t)(m0 + row) * ND + k0 + kc);
            rb[u] = *(const float4*)(BT + (size_t)(n0 + row) * ND + k0 + kc);
        }
        __syncthreads();
#pragma unroll
        for (int u = 0; u < 4; ++u) {
            const int f = (u << 8) + tid;
            const int row = f >> 3, kc = (f & 7) << 2;
            uint4 ta, tb;
            ta.x = f2tf32(ra[u].x); ta.y = f2tf32(ra[u].y);
            ta.z = f2tf32(ra[u].z); ta.w = f2tf32(ra[u].w);
            tb.x = f2tf32(rb[u].x); tb.y = f2tf32(rb[u].y);
            tb.z = f2tf32(rb[u].z); tb.w = f2tf32(rb[u].w);
            *(uint4*)&As[row][kc] = ta;
            *(uint4*)&Bs[row][kc] = tb;
        }
        __syncthreads();

#pragma unroll
        for (int ks = 0; ks < 4; ++ks) {
            const int kk = ks << 3;
            uint32_t af[2][4];
#pragma unroll
            for (int mt = 0; mt < 2; ++mt) {
                const int rb_ = (wm << 5) + (mt << 4);
                af[mt][0] = __float_as_uint(As[rb_ + g    ][kk + t]);
                af[mt][1] = __float_as_uint(As[rb_ + g + 8][kk + t]);
                af[mt][2] = __float_as_uint(As[rb_ + g    ][kk + t + 4]);
                af[mt][3] = __float_as_uint(As[rb_ + g + 8][kk + t + 4]);
            }
#pragma unroll
            for (int nt = 0; nt < 8; ++nt) {
                const int cb = (wn << 6) + (nt << 3) + g;
                const uint32_t b0 = __float_as_uint(Bs[cb][kk + t]);
                const uint32_t b1 = __float_as_uint(Bs[cb][kk + t + 4]);
                mma8(acc[0][nt], af[0], b0, b1);
                mma8(acc[1][nt], af[1], b0, b1);
            }
        }
    }

    // epilogue
#pragma unroll
    for (int mt = 0; mt < 2; ++mt) {
#pragma unroll
        for (int nt = 0; nt < 8; ++nt) {
            const int r0 = m0 + (wm << 5) + (mt << 4) + g;
            const int cc = n0 + (wn << 6) + (nt << 3) + (t << 1);
#pragma unroll
            for (int h = 0; h < 2; ++h) {
                const int m = r0 + (h << 3);
                float v0 = acc[mt][nt][h * 2 + 0];
                float v1 = acc[mt][nt][h * 2 + 1];
                if (MODE == 0) {
                    const int bb = m >> 11, tt = m & (NT - 1);
                    const int hh = cc >> 6, d = cc & 63;
                    float* dst = g_Q; (void)dst;   // placeholder, overwritten below
                    float* o = Out + (((((size_t)bb * NHH + hh) * NT + tt) << 6) + d);
                    o[0] = v0; o[1] = v1;
                } else {
                    v0 += bias[cc]; v1 += bias[cc + 1];
                    float* o = Out + (size_t)m * ND + cc;
                    o[0] = v0; o[1] = v1;
                }
            }
        }
    }
}

// ---------------------------------------------------------------------------
// Causal flash attention with tf32 mma.sync.
// Block: 64 q-rows, 128 threads = 4 warps, each warp owns 16 q-rows.
// ---------------------------------------------------------------------------
#define QS_STR 68
#define VS_STR 72
__global__ void __launch_bounds__(128) attn_mma(
    const uint8_t* __restrict__ kpm, float* __restrict__ Cctx)
{
    extern __shared__ float sm[];
    float* Qs  = sm;                         // 64 x 68
    float* Ks  = Qs + 64 * QS_STR;           // 64 x 68
    float* Vs  = Ks + 64 * QS_STR;           // 64 x 72
    float* Msk = Vs + 64 * VS_STR;           // 64

    const int tid  = threadIdx.x;
    const int lane = tid & 31;
    const int wq   = tid >> 5;               // warp's q sub-tile (16 rows)
    const int g = lane >> 2, t = lane & 3;
    const int qt = blockIdx.x;
    const int bh = blockIdx.y;
    const int bb = bh >> 4, hh = bh & 15;
    const int q0 = qt << 6;

    const float* Qg = g_Q + ((size_t)bh * NT << 6);
    const float* Kg = g_K + ((size_t)bh * NT << 6);
    const float* Vg = g_V + ((size_t)bh * NT << 6);

    // load Q (tf32-rounded)
    for (int f = tid; f < 64 * 16; f += 128) {
        const int r = f >> 4, d4 = (f & 15) << 2;
        float4 v = *(const float4*)&Qg[((q0 + r) << 6) + d4];
        uint4 u;
        u.x = f2tf32(v.x); u.y = f2tf32(v.y);
        u.z = f2tf32(v.z); u.w = f2tf32(v.w);
        *(uint4*)&Qs[r * QS_STR + d4] = u;
    }
    __syncthreads();

    // preload Q fragments (8 k-steps over d=64)
    uint32_t qf[8][4];
    const int qrow = (wq << 4) + g;
#pragma unroll
    for (int ks = 0; ks < 8; ++ks) {
        const int kk = ks << 3;
        qf[ks][0] = __float_as_uint(Qs[(qrow    ) * QS_STR + kk + t]);
        qf[ks][1] = __float_as_uint(Qs[(qrow + 8) * QS_STR + kk + t]);
        qf[ks][2] = __float_as_uint(Qs[(qrow    ) * QS_STR + kk + t + 4]);
        qf[ks][3] = __float_as_uint(Qs[(qrow + 8) * QS_STR + kk + t + 4]);
    }

    const int r0 = q0 + (wq << 4) + g;       // this thread's two q rows
    const int r1 = r0 + 8;
    float m0 = -1e30f, m1 = -1e30f, l0 = 0.f, l1 = 0.f;
    float oacc[8][4];
#pragma unroll
    for (int dt = 0; dt < 8; ++dt)
#pragma unroll
        for (int e = 0; e < 4; ++e) oacc[dt][e] = 0.f;

    for (int kt = 0; kt <= qt; ++kt) {
        const int k0 = kt << 6;
        __syncthreads();   // previous iter's mma reads done
        for (int f = tid; f < 64 * 16; f += 128) {
            const int r = f >> 4, d4 = (f & 15) << 2;
            float4 kv = *(const float4*)&Kg[((k0 + r) << 6) + d4];
            float4 vv = *(const float4*)&Vg[((k0 + r) << 6) + d4];
            uint4 uk, uv;
            uk.x = f2tf32(kv.x); uk.y = f2tf32(kv.y);
            uk.z = f2tf32(kv.z); uk.w = f2tf32(kv.w);
            uv.x = f2tf32(vv.x); uv.y = f2tf32(vv.y);
            uv.z = f2tf32(vv.z); uv.w = f2tf32(vv.w);
            *(uint4*)&Ks[r * QS_STR + d4] = uk;
            *(uint4*)&Vs[r * VS_STR + d4] = uv;
        }
        if (tid < 64)
            Msk[tid] = kpm[bb * NT + k0 + tid] ? -1e30f : 0.f;
        __syncthreads();

        // ---- S = Q K^T ----
        float sacc[8][4];
#pragma unroll
        for (int nt = 0; nt < 8; ++nt)
#pragma unroll
            for (int e = 0; e < 4; ++e) sacc[nt][e] = 0.f;

#pragma unroll
        for (int ks = 0; ks < 8; ++ks) {
            const int kk = ks << 3;
#pragma unroll
            for (int nt = 0; nt < 8; ++nt) {
                const int kr = (nt << 3) + g;
                const uint32_t b0 = __float_as_uint(Ks[kr * QS_STR + kk + t]);
                const uint32_t b1 = __float_as_uint(Ks[kr * QS_STR + kk + t + 4]);
                mma8(sacc[nt], qf[ks], b0, b1);
            }
        }

        // ---- scale + masks ----
        const bool diag = (kt == qt);
        float mx0 = -1e30f, mx1 = -1e30f;
#pragma unroll
        for (int nt = 0; nt < 8; ++nt) {
            const int cl = (nt << 3) + (t << 1);
            const int kv0 = k0 + cl, kv1 = kv0 + 1;
            const float pm0 = Msk[cl], pm1 = Msk[cl + 1];
            float s0 = sacc[nt][0] * 0.125f + pm0;
            float s1 = sacc[nt][1] * 0.125f + pm1;
            float s2 = sacc[nt][2] * 0.125f + pm0;
            float s3 = sacc[nt][3] * 0.125f + pm1;
            if (diag) {
                if (kv0 > r0) s0 = -1e30f;
                if (kv1 > r0) s1 = -1e30f;
                if (kv0 > r1) s2 = -1e30f;
                if (kv1 > r1) s3 = -1e30f;
            }
            sacc[nt][0] = s0; sacc[nt][1] = s1;
            sacc[nt][2] = s2; sacc[nt][3] = s3;
            mx0 = fmaxf(mx0, fmaxf(s0, s1));
            mx1 = fmaxf(mx1, fmaxf(s2, s3));
        }
        mx0 = fmaxf(mx0, __shfl_xor_sync(0xffffffffu, mx0, 1));
        mx0 = fmaxf(mx0, __shfl_xor_sync(0xffffffffu, mx0, 2));
        mx1 = fmaxf(mx1, __shfl_xor_sync(0xffffffffu, mx1, 1));
        mx1 = fmaxf(mx1, __shfl_xor_sync(0xffffffffu, mx1, 2));

        const float nm0 = fmaxf(m0, mx0), nm1 = fmaxf(m1, mx1);
        const float cr0 = __expf(m0 - nm0), cr1 = __expf(m1 - nm1);
        m0 = nm0; m1 = nm1;

        float sum0 = 0.f, sum1 = 0.f;
#pragma unroll
        for (int nt = 0; nt < 8; ++nt) {
            float p0 = __expf(sacc[nt][0] - nm0);
            float p1 = __expf(sacc[nt][1] - nm0);
            float p2 = __expf(sacc[nt][2] - nm1);
            float p3 = __expf(sacc[nt][3] - nm1);
            sacc[nt][0] = p0; sacc[nt][1] = p1;
            sacc[nt][2] = p2; sacc[nt][3] = p3;
            sum0 += p0 + p1; sum1 += p2 + p3;
        }
        sum0 += __shfl_xor_sync(0xffffffffu, sum0, 1);
        sum0 += __shfl_xor_sync(0xffffffffu, sum0, 2);
        sum1 += __shfl_xor_sync(0xffffffffu, sum1, 1);
        sum1 += __shfl_xor_sync(0xffffffffu, sum1, 2);
        l0 = l0 * cr0 + sum0;
        l1 = l1 * cr1 + sum1;
#pragma unroll
        for (int dt = 0; dt < 8; ++dt) {
            oacc[dt][0] *= cr0; oacc[dt][1] *= cr0;
            oacc[dt][2] *= cr1; oacc[dt][3] *= cr1;
        }

        // ---- O += P V ----
        const int srcA = (lane & ~3) | (t >> 1);
        const int srcB = srcA + 2;
        const bool odd = (t & 1);
#pragma unroll
        for (int kk = 0; kk < 8; ++kk) {
            const float pA0 = __shfl_sync(0xffffffffu, sacc[kk][0], srcA);
            const float pA1 = __shfl_sync(0xffffffffu, sacc[kk][1], srcA);
            const float pB0 = __shfl_sync(0xffffffffu, sacc[kk][0], srcB);
            const float pB1 = __shfl_sync(0xffffffffu, sacc[kk][1], srcB);
            const float pC0 = __shfl_sync(0xffffffffu, sacc[kk][2], srcA);
            const float pC1 = __shfl_sync(0xffffffffu, sacc[kk][3], srcA);
            const float pD0 = __shfl_sync(0xffffffffu, sacc[kk][2], srcB);
            const float pD1 = __shfl_sync(0xffffffffu, sacc[kk][3], srcB);
            uint32_t a[4];
            a[0] = f2tf32(odd ? pA1 : pA0);
            a[1] = f2tf32(odd ? pC1 : pC0);
            a[2] = f2tf32(odd ? pB1 : pB0);
            a[3] = f2tf32(odd ? pD1 : pD0);
#pragma unroll
            for (int dt = 0; dt < 8; ++dt) {
                const int dc = (dt << 3) + g;
                const uint32_t b0 = __float_as_uint(Vs[((kk << 3) + t    ) * VS_STR + dc]);
                const uint32_t b1 = __float_as_uint(Vs[((kk << 3) + t + 4) * VS_STR + dc]);
                mma8(oacc[dt], a, b0, b1);
            }
        }
    }

    // ---- normalize + write ctx [b*T+t, h*64+d] ----
    const float i0 = 1.f / l0, i1 = 1.f / l1;
    const int mrow0 = (bb << 11) + q0 + (wq << 4) + g;
#pragma unroll
    for (int dt = 0; dt < 8; ++dt) {
        const int dc = (hh << 6) + (dt << 3) + (t << 1);
        float* o0 = Cctx + (size_t)mrow0 * ND + dc;
        float* o1 = Cctx + (size_t)(mrow0 + 8) * ND + dc;
        o0[0] = oacc[dt][0] * i0; o0[1] = oacc[dt][1] * i0;
        o1[0] = oacc[dt][2] * i1; o1[1] = oacc[dt][3] * i1;
    }
}

// ---------------------------------------------------------------------------
extern "C" void kernel_launch(void* const* d_in, const int* in_sizes, int n_in,
                              void* d_out, int out_size)
{
    (void)in_sizes; (void)n_in; (void)out_size;
    const float*   x   = (const float*)d_in[0];
    const float*   Wq  = (const float*)d_in[1];
    const float*   Wk  = (const float*)d_in[2];
    const float*   Wv  = (const float*)d_in[3];
    const float*   Wo  = (const float*)d_in[4];
    const float*   bo  = (const float*)d_in[5];
    const uint8_t* kpm = (const uint8_t*)d_in[6];
    float* out = (float*)d_out;

    float *Qp, *Kp, *Vp, *Cp, *WTp;
    cudaGetSymbolAddress((void**)&Qp, g_Q);
    cudaGetSymbolAddress((void**)&Kp, g_K);
    cudaGetSymbolAddress((void**)&Vp, g_V);
    cudaGetSymbolAddress((void**)&Cp, g_C);
    cudaGetSymbolAddress((void**)&WTp, g_WT);

    const dim3 tg(32, 32), tb(32, 8);
    transpose_w<<<tg, tb>>>(Wq, WTp + 0 * ND * ND);
    transpose_w<<<tg, tb>>>(Wk, WTp + 1 * ND * ND);
    transpose_w<<<tg, tb>>>(Wv, WTp + 2 * ND * ND);
    transpose_w<<<tg, tb>>>(Wo, WTp + 3 * ND * ND);

    const dim3 gg(ND / 128, NM / 128);   // (8, 32)
    gemm_mma<0><<<gg, 256>>>(x, WTp + 0 * ND * ND, Qp, nullptr);
    gemm_mma<0><<<gg, 256>>>(x, WTp + 1 * ND * ND, Kp, nullptr);
    gemm_mma<0><<<gg, 256>>>(x, WTp + 2 * ND * ND, Vp, nullptr);

    const int asmem = (64 * QS_STR * 2 + 64 * VS_STR + 64) * (int)sizeof(float);
    cudaFuncSetAttribute(attn_mma, cudaFuncAttributeMaxDynamicSharedMemorySize, asmem);
    attn_mma<<<dim3(NT / 64, NB * NHH), 128, asmem>>>(kpm, Cp);

    gemm_mma<1><<<gg, 256>>>(Cp, WTp + 3 * ND * ND, out, bo);
}